// round 13
// baseline (speedup 1.0000x reference)
#include <cuda_runtime.h>
#include <cuda_bf16.h>
#include <stdint.h>

#define NUM_USERS 100000
#define NUM_ITEMS 50000
#define N_NODES   (NUM_USERS + NUM_ITEMS)   // 150000
#define EMBED_DIM 64
#define N_EDGES   1000000

#define CSR_MAX   (N_EDGES + 3 * N_NODES)   // padded-to-4 upper bound (1.45M)

#define SCAN_BS   1024
#define N_SCAN_BLOCKS ((N_NODES + SCAN_BS - 1) / SCAN_BS)   // 147

#define A_FLAG (1u << 30)
#define P_FLAG (1u << 31)
#define VAL_MASK 0x3FFFFFFFu

// ---- static device scratch (no allocation allowed) ----
__device__ int      g_deg[N_NODES];
__device__ float    g_dinv[N_NODES];
__device__ int      g_off[N_NODES];          // exclusive prefix of PADDED degrees (immutable)
__device__ int      g_cur[N_NODES];          // scatter cursors (memset 0)
__device__ unsigned g_part[N_SCAN_BLOCKS];   // lookback state (memset 0)
__device__ int4     g_csr4[CSR_MAX / 2];     // {src,norm} pairs, 2 per int4, memset 0
__device__ float    g_x1[N_NODES * EMBED_DIM];
__device__ float    g_x2[N_NODES * EMBED_DIM];

// -------------------- setup kernels --------------------

// 2 edges per thread, vectorized int2 loads
__global__ void k_degree(const int* __restrict__ edge_index) {
    int t = blockIdx.x * blockDim.x + threadIdx.x;
    if (t < N_EDGES / 2) {
        int2 d2 = ((const int2*)(edge_index + N_EDGES))[t];
        atomicAdd(&g_deg[d2.x], 1);
        atomicAdd(&g_deg[d2.y], 1);
    }
}

// single-pass decoupled-lookback exclusive scan of PADDED degrees; emits dinv.
__global__ void __launch_bounds__(SCAN_BS) k_scan() {
    __shared__ int s_wt[32];
    __shared__ int s_run;

    int tid  = threadIdx.x;
    int bid  = blockIdx.x;
    int lane = tid & 31;
    int wid  = tid >> 5;
    int i    = bid * SCAN_BS + tid;

    int d  = (i < N_NODES) ? g_deg[i] : 0;
    if (i < N_NODES) g_dinv[i] = (d > 0) ? rsqrtf((float)d) : 0.0f;
    int v = (d + 3) & ~3;                    // padded degree

    int inc = v;
    #pragma unroll
    for (int s = 1; s < 32; s <<= 1) {
        int t = __shfl_up_sync(0xffffffffu, inc, s);
        if (lane >= s) inc += t;
    }
    if (lane == 31) s_wt[wid] = inc;
    __syncthreads();

    if (wid == 0) {
        int wv = s_wt[lane];
        int winc = wv;
        #pragma unroll
        for (int s = 1; s < 32; s <<= 1) {
            int t = __shfl_up_sync(0xffffffffu, winc, s);
            if (lane >= s) winc += t;
        }
        s_wt[lane] = winc;
        if (lane == 31)
            atomicExch(&g_part[bid], A_FLAG | (unsigned)winc);

        int running = 0;
        int look = bid - 1;
        while (look >= 0) {
            int idx = look - lane;
            unsigned w;
            if (idx >= 0) {
                volatile unsigned* p = (volatile unsigned*)&g_part[idx];
                do { w = *p; } while ((w & (A_FLAG | P_FLAG)) == 0);
            } else {
                w = P_FLAG;
            }
            unsigned pm = __ballot_sync(0xffffffffu, (w & P_FLAG) != 0);
            int firstP = pm ? (__ffs(pm) - 1) : 32;
            int contrib = (lane <= firstP) ? (int)(w & VAL_MASK) : 0;
            #pragma unroll
            for (int s = 16; s; s >>= 1) contrib += __shfl_down_sync(0xffffffffu, contrib, s);
            contrib = __shfl_sync(0xffffffffu, contrib, 0);
            running += contrib;
            if (firstP < 32) break;
            look -= 32;
        }
        if (lane == 31)
            atomicExch(&g_part[bid], P_FLAG | (unsigned)(running + winc));
        if (lane == 0) s_run = running;
    }
    __syncthreads();

    int excl = (wid ? s_wt[wid - 1] : 0) + (inc - v) + s_run;
    if (i < N_NODES) g_off[i] = excl;
}

// scatter 2 edges per thread into padded CSR; g_off stays immutable.
__global__ void k_scatter(const int* __restrict__ edge_index) {
    int t = blockIdx.x * blockDim.x + threadIdx.x;
    if (t < N_EDGES / 2) {
        int2* csr = (int2*)g_csr4;
        int2 s2 = ((const int2*)edge_index)[t];
        int2 d2 = ((const int2*)(edge_index + N_EDGES))[t];
        {
            int pos = g_off[d2.x] + atomicAdd(&g_cur[d2.x], 1);
            float norm = g_dinv[s2.x] * g_dinv[d2.x];
            csr[pos] = make_int2(s2.x, __float_as_int(norm));
        }
        {
            int pos = g_off[d2.y] + atomicAdd(&g_cur[d2.y], 1);
            float norm = g_dinv[s2.y] * g_dinv[d2.y];
            csr[pos] = make_int2(s2.y, __float_as_int(norm));
        }
    }
}

// -------------------- propagation --------------------
// 2 nodes per warp: 16 lanes per node, float4 per lane (16 x 16B = 256B row).
// Padded CSR: every segment is a multiple of 4 edges, 16B-aligned. Each trip:
// 2x int4 csr loads (4 edges) + 4 gather LDG.128 — zero clamping ALU.
__device__ __forceinline__ float4 gather_node4(const float4* __restrict__ xin,
                                               int beg, int ntrips, int qlane) {
    float4 sum = make_float4(0.0f, 0.0f, 0.0f, 0.0f);
    int h = beg >> 1;                            // int4 index (beg is multiple of 4)
    for (int t = 0; t < ntrips; t++, h += 2) {
        int4 c01 = g_csr4[h];                    // {src0, w0, src1, w1}
        int4 c23 = g_csr4[h + 1];                // {src2, w2, src3, w3}
        float4 v0 = xin[c01.x * 16 + qlane];
        float4 v1 = xin[c01.z * 16 + qlane];
        float4 v2 = xin[c23.x * 16 + qlane];
        float4 v3 = xin[c23.z * 16 + qlane];
        float w0 = __int_as_float(c01.y);
        float w1 = __int_as_float(c01.w);
        float w2 = __int_as_float(c23.y);
        float w3 = __int_as_float(c23.w);
        sum.x = fmaf(v0.x, w0, sum.x);  sum.y = fmaf(v0.y, w0, sum.y);
        sum.z = fmaf(v0.z, w0, sum.z);  sum.w = fmaf(v0.w, w0, sum.w);
        sum.x = fmaf(v1.x, w1, sum.x);  sum.y = fmaf(v1.y, w1, sum.y);
        sum.z = fmaf(v1.z, w1, sum.z);  sum.w = fmaf(v1.w, w1, sum.w);
        sum.x = fmaf(v2.x, w2, sum.x);  sum.y = fmaf(v2.y, w2, sum.y);
        sum.z = fmaf(v2.z, w2, sum.z);  sum.w = fmaf(v2.w, w2, sum.w);
        sum.x = fmaf(v3.x, w3, sum.x);  sum.y = fmaf(v3.y, w3, sum.y);
        sum.z = fmaf(v3.z, w3, sum.z);  sum.w = fmaf(v3.w, w3, sum.w);
    }
    return sum;
}

__global__ void __launch_bounds__(256) k_prop1(const float4* __restrict__ emb) {
    int gtid = blockIdx.x * blockDim.x + threadIdx.x;
    int node = gtid >> 4, qlane = gtid & 15;
    if (node >= N_NODES) return;
    int beg = g_off[node];
    int nt  = (g_deg[node] + 3) >> 2;
    float4 sum = gather_node4(emb, beg, nt, qlane);
    ((float4*)g_x1)[(size_t)node * 16 + qlane] = sum;
}

__global__ void __launch_bounds__(256) k_prop2() {
    int gtid = blockIdx.x * blockDim.x + threadIdx.x;
    int node = gtid >> 4, qlane = gtid & 15;
    if (node >= N_NODES) return;
    int beg = g_off[node];
    int nt  = (g_deg[node] + 3) >> 2;
    float4 sum = gather_node4((const float4*)g_x1, beg, nt, qlane);
    ((float4*)g_x2)[(size_t)node * 16 + qlane] = sum;
}

// layer 3 + epilogue: out = 0.25*(emb + l1 + l2 + A~*l2)
__global__ void __launch_bounds__(256) k_prop_last(const float4* __restrict__ emb,
                                                   float4* __restrict__ out) {
    int gtid = blockIdx.x * blockDim.x + threadIdx.x;
    int node = gtid >> 4, qlane = gtid & 15;
    if (node >= N_NODES) return;
    int beg = g_off[node];
    int nt  = (g_deg[node] + 3) >> 2;
    float4 sum = gather_node4((const float4*)g_x2, beg, nt, qlane);

    size_t oi = (size_t)node * 16 + qlane;
    float4 e0 = emb[oi];
    float4 a1 = ((const float4*)g_x1)[oi];
    float4 a2 = ((const float4*)g_x2)[oi];
    float4 o;
    o.x = 0.25f * (e0.x + a1.x + a2.x + sum.x);
    o.y = 0.25f * (e0.y + a1.y + a2.y + sum.y);
    o.z = 0.25f * (e0.z + a1.z + a2.z + sum.z);
    o.w = 0.25f * (e0.w + a1.w + a2.w + sum.w);
    out[oi] = o;
}

// -------------------- launch --------------------

extern "C" void kernel_launch(void* const* d_in, const int* in_sizes, int n_in,
                              void* d_out, int out_size) {
    const int*   edge_index = (const int*)d_in[0];     // int32
    const float* emb_weight = (const float*)d_in[1];
    float*       out        = (float*)d_out;

    void *deg_ptr, *part_ptr, *cur_ptr, *csr_ptr;
    cudaGetSymbolAddress(&deg_ptr,  g_deg);
    cudaGetSymbolAddress(&part_ptr, g_part);
    cudaGetSymbolAddress(&cur_ptr,  g_cur);
    cudaGetSymbolAddress(&csr_ptr,  g_csr4);
    cudaMemsetAsync(deg_ptr,  0, N_NODES * sizeof(int), 0);
    cudaMemsetAsync(part_ptr, 0, N_SCAN_BLOCKS * sizeof(unsigned), 0);
    cudaMemsetAsync(cur_ptr,  0, N_NODES * sizeof(int), 0);
    cudaMemsetAsync(csr_ptr,  0, (CSR_MAX / 2) * sizeof(int4), 0);

    const int BS = 256;
    int geh = (N_EDGES / 2 + BS - 1) / BS;

    k_degree<<<geh, BS>>>(edge_index);               // kernel 1
    k_scan<<<N_SCAN_BLOCKS, SCAN_BS>>>();            // kernel 2
    k_scatter<<<geh, BS>>>(edge_index);              // kernel 3

    int gp = (N_NODES * 16 + BS - 1) / BS;           // 16 threads per node
    k_prop1<<<gp, BS>>>((const float4*)emb_weight);            // kernel 4 <- ncu
    k_prop2<<<gp, BS>>>();                                     // kernel 5
    k_prop_last<<<gp, BS>>>((const float4*)emb_weight, (float4*)out); // kernel 6
}